// round 10
// baseline (speedup 1.0000x reference)
#include <cuda_runtime.h>
#include <cuda_fp16.h>
#include <cstdint>

#define BB 2
#define SS 4096
#define DD 768
#define HH 12
#define HDD 64

// Scratch (device globals: no allocations allowed in kernel_launch)
__device__ __half g_qkvh[3*BB*SS*DD];  // q(x0.125) | k | vT[b][h][hd][s]
__device__ __half g_ctxh[BB*SS*DD];    // attn output, fp16
__device__ __half g_xh[BB*SS*DD];      // fp16 x
__device__ __half g_wh[4*DD*DD];       // fp16 wq,wk,wv,wo

__device__ __forceinline__ uint32_t packh2(float lo, float hi) {
    __half2 h = __floats2half2_rn(lo, hi);
    return *reinterpret_cast<uint32_t*>(&h);
}

__device__ __forceinline__ void mma_f16(
    float& d0, float& d1, float& d2, float& d3,
    uint32_t a0, uint32_t a1, uint32_t a2, uint32_t a3,
    uint32_t b0, uint32_t b1)
{
    asm volatile(
        "mma.sync.aligned.m16n8k16.row.col.f32.f16.f16.f32 "
        "{%0,%1,%2,%3}, {%4,%5,%6,%7}, {%8,%9}, {%0,%1,%2,%3};\n"
        : "+f"(d0), "+f"(d1), "+f"(d2), "+f"(d3)
        : "r"(a0), "r"(a1), "r"(a2), "r"(a3), "r"(b0), "r"(b1));
}

// ldmatrix x4: 4 8x8 b16 matrices; lanes 0-7/8-15/16-23/24-31 give row addrs
__device__ __forceinline__ void ldsm4(
    uint32_t& r0, uint32_t& r1, uint32_t& r2, uint32_t& r3, const void* p)
{
    uint32_t a = (uint32_t)__cvta_generic_to_shared(p);
    asm volatile("ldmatrix.sync.aligned.m8n8.x4.shared.b16 {%0,%1,%2,%3}, [%4];"
                 : "=r"(r0), "=r"(r1), "=r"(r2), "=r"(r3) : "r"(a));
}

__device__ __forceinline__ void cpa16(void* dst, const void* src) {
    uint32_t d = (uint32_t)__cvta_generic_to_shared(dst);
    asm volatile("cp.async.ca.shared.global [%0], [%1], 16;\n" :: "r"(d), "l"(src));
}
#define CP_COMMIT asm volatile("cp.async.commit_group;\n" ::: "memory")
#define CP_WAIT0  asm volatile("cp.async.wait_group 0;\n" ::: "memory")

// ---------------------------------------------------------------------------
// fused fp32 -> fp16 conversion: blockIdx.y selects x / wq / wk / wv / wo
// ---------------------------------------------------------------------------
__global__ void conv_half(const float4* __restrict__ x,
                          const float4* __restrict__ wq, const float4* __restrict__ wk,
                          const float4* __restrict__ wv, const float4* __restrict__ wo,
                          __half* __restrict__ xh, __half* __restrict__ wh)
{
    const int nx4 = BB*SS*DD/4, nw4 = DD*DD/4;
    const int z = blockIdx.y;
    const float4* src; __half* dst; int n4;
    if (z == 0) { src = x; dst = xh; n4 = nx4; }
    else {
        src = (z == 1) ? wq : (z == 2) ? wk : (z == 3) ? wv : wo;
        dst = wh + (size_t)(z-1) * DD*DD;
        n4 = nw4;
    }
    int i = blockIdx.x * blockDim.x + threadIdx.x;
    if (i < n4) {
        float4 v = src[i];
        __half2* d2 = (__half2*)(dst + 4*(size_t)i);
        d2[0] = __floats2half2_rn(v.x, v.y);
        d2[1] = __floats2half2_rn(v.z, v.w);
    }
}

// ---------------------------------------------------------------------------
// fp16 GEMM: C[M,N] = A[M,K] @ W[N,K]^T (+bias). CTA 128x128, BK=64,
// 8 warps (2x4) of 64x32, m16n8k16 fp16 mma, fragments via ldmatrix.x4.
// 2-stage cp.async pipeline. Stride 72 halves (36 wd ==4 mod 32): the 8 rows
// of each 8x8 ldmatrix tile start at banks 4r..4r+3 -> conflict-free.
// mode==0: fp32 out + bias (out-proj).  mode==1: QKV via blockIdx.z:
//   Q (x0.125) | K plain | V transposed vt[b][h][hd][s].
// ---------------------------------------------------------------------------
#define GLH 72
#define GSTGH (128*GLH)

__global__ __launch_bounds__(256) void gemm_f16(
    const __half* __restrict__ A, const __half* __restrict__ Wbase,
    const float* __restrict__ bias, float* __restrict__ Cf,
    __half* __restrict__ Ch, int mode)
{
    extern __shared__ __half hsm[];
    __half* As = hsm;                 // 2 stages x 128 x GLH
    __half* Ws = hsm + 2*GSTGH;

    const int K = DD, N = DD;
    const __half* W = Wbase + (size_t)blockIdx.z * DD*DD;

    const int tid  = threadIdx.x;
    const int lane = tid & 31;
    const int warp = tid >> 5;
    const int g = lane >> 2, tig = lane & 3;
    const int wm = warp & 1;
    const int wn = warp >> 1;
    const int bm = blockIdx.y * 128;
    const int bn = blockIdx.x * 128;
    const int lrow  = lane & 15;          // ldmatrix row-within-16
    const int khalf = (lane >> 4) << 3;   // +8 halves for matrices 2,3

    float acc[4][4][4];
#pragma unroll
    for (int mi = 0; mi < 4; mi++)
#pragma unroll
        for (int ni = 0; ni < 4; ni++)
#pragma unroll
            for (int c = 0; c < 4; c++) acc[mi][ni][c] = 0.f;

    const int nk = K / 64;            // 12

    {
#pragma unroll
        for (int i = 0; i < 8; i++) {
            const int id = tid + 256*i;
            if (id < 1024) {          // A: 128 rows x 8 chunks of 8 halves
                const int r = id >> 3, c = id & 7;
                cpa16(&As[r*GLH + c*8], A + (size_t)(bm + r)*K + c*8);
            } else {
                const int id2 = id - 1024, r = id2 >> 3, c = id2 & 7;
                cpa16(&Ws[r*GLH + c*8], W + (size_t)(bn + r)*K + c*8);
            }
        }
        CP_COMMIT;
    }

    for (int it = 0; it < nk; it++) {
        CP_WAIT0;
        __syncthreads();
        const int s = it & 1;
        if (it + 1 < nk) {
            const int k1 = (it + 1) * 64;
            __half* Ad = As + (s^1)*GSTGH;
            __half* Wd = Ws + (s^1)*GSTGH;
#pragma unroll
            for (int i = 0; i < 8; i++) {
                const int id = tid + 256*i;
                if (id < 1024) {
                    const int r = id >> 3, c = id & 7;
                    cpa16(&Ad[r*GLH + c*8], A + (size_t)(bm + r)*K + k1 + c*8);
                } else {
                    const int id2 = id - 1024, r = id2 >> 3, c = id2 & 7;
                    cpa16(&Wd[r*GLH + c*8], W + (size_t)(bn + r)*K + k1 + c*8);
                }
            }
            CP_COMMIT;
        }
        const __half* Ab = As + s*GSTGH;
        const __half* Wb = Ws + s*GSTGH;
#pragma unroll
        for (int kk = 0; kk < 4; kk++) {     // 4 k-chunks of 16
            uint32_t b0[4], b1[4];
#pragma unroll
            for (int nip = 0; nip < 2; nip++)
                ldsm4(b0[2*nip], b0[2*nip+1], b1[2*nip], b1[2*nip+1],
                      &Wb[(32*wn + 16*nip + lrow)*GLH + 16*kk + khalf]);
#pragma unroll
            for (int mi = 0; mi < 4; mi++) {
                uint32_t a0, a1, a2, a3;
                ldsm4(a0, a1, a2, a3,
                      &Ab[(64*wm + 16*mi + lrow)*GLH + 16*kk + khalf]);
#pragma unroll
                for (int ni = 0; ni < 4; ni++)
                    mma_f16(acc[mi][ni][0], acc[mi][ni][1],
                            acc[mi][ni][2], acc[mi][ni][3],
                            a0, a1, a2, a3, b0[ni], b1[ni]);
            }
        }
    }

    const int z = blockIdx.z;
#pragma unroll
    for (int ni = 0; ni < 4; ni++) {
        const int col = bn + 32*wn + 8*ni + 2*tig;
        float bx = 0.f, by = 0.f;
        if (mode == 0 && bias) { bx = bias[col]; by = bias[col+1]; }
#pragma unroll
        for (int mi = 0; mi < 4; mi++) {
            const int r0 = bm + 64*wm + 16*mi + g;
            float v0 = acc[mi][ni][0] + bx, v1 = acc[mi][ni][1] + by;
            float v2 = acc[mi][ni][2] + bx, v3 = acc[mi][ni][3] + by;
            if (mode == 0) {
                *(float2*)(Cf + (size_t)r0*N + col)     = make_float2(v0, v1);
                *(float2*)(Cf + (size_t)(r0+8)*N + col) = make_float2(v2, v3);
                continue;
            }
            __half* C = Ch + (size_t)z * BB*SS*DD;
            if (z == 0) {                 // Q, pre-scaled by 1/8 (exact)
                v0 *= 0.125f; v1 *= 0.125f; v2 *= 0.125f; v3 *= 0.125f;
            }
            if (z <= 1) {                 // Q/K: plain [s][768] fp16
                *(__half2*)(C + (size_t)r0*N + col) = __floats2half2_rn(v0, v1);
                *(__half2*)(C + (size_t)(r0+8)*N + col) = __floats2half2_rn(v2, v3);
            } else {                      // V transposed: vt[((b*HH+h)*64+hd)][s]
                const int h = col >> 6, hd = col & 63;
#pragma unroll
                for (int rr = 0; rr < 2; rr++) {
                    const int r = r0 + 8*rr;
                    const int b = r >> 12, sq = r & (SS-1);
                    __half* vp = C + ((size_t)((b*HH + h)*HDD + hd))*SS + sq;
                    vp[0]  = __float2half_rn(rr ? v2 : v0);
                    vp[SS] = __float2half_rn(rr ? v3 : v1);
                }
            }
        }
    }
}

// ---------------------------------------------------------------------------
// Flash attention, fp16 m16n8k16 mma, fp32 accum + softmax.
// 8 warps (16-row bands), BQ=128, BK=64; K/V double-buffered cp.async.
// Q pre-scaled 1/8; K and V^T fragments via ldmatrix.x4 (4 instr per kk).
// PV A-frag packed from S regs in natural key order (V^T gives standard
// B binding). Strides 72 halves everywhere -> ldmatrix conflict-free.
// ---------------------------------------------------------------------------
#define KLH 72

__global__ __launch_bounds__(256, 2) void attn_f16()
{
    extern __shared__ __half hsmm[];
    __half* Qs  = hsmm;                       // 128 x KLH
    __half* Ksb = hsmm + 128*KLH;             // 2 x 64 x KLH
    __half* Vsb = Ksb + 2*64*KLH;             // 2 x 64(hd) x KLH (keys)

    const int tid  = threadIdx.x;
    const int lane = tid & 31;
    const int warp = tid >> 5;                // 0..7 -> 16-row band
    const int g = lane >> 2, tig = lane & 3;
    const int lrow  = lane & 15;
    const int khalf = (lane >> 4) << 3;
    const int bh = blockIdx.y;
    const int b  = bh / HH;
    const int h  = bh % HH;
    const int qt = (gridDim.x - 1) - blockIdx.x;   // heavy tiles first
    const int q0 = qt * 128;

    const __half* Qg = g_qkvh + 0*BB*SS*DD + ((size_t)b * SS) * DD + h * HDD;
    const __half* Kg = g_qkvh + 1*BB*SS*DD + ((size_t)b * SS) * DD + h * HDD;
    const __half* Vg = g_qkvh + 2*BB*SS*DD + ((size_t)(b*HH + h) * HDD) * SS;

    // prologue: Q tile + K/V tile 0
    {
#pragma unroll
        for (int i = 0; i < 4; i++) {             // Q: 128 rows x 8 chunks
            const int id = tid + 256*i;
            const int r = id >> 3, c = id & 7;
            cpa16(&Qs[r*KLH + c*8], Qg + (size_t)(q0 + r)*DD + c*8);
        }
#pragma unroll
        for (int i = 0; i < 2; i++) {             // K: 64 rows x 8 chunks
            const int id = tid + 256*i;
            const int r = id >> 3, c = id & 7;
            cpa16(&Ksb[r*KLH + c*8], Kg + (size_t)r*DD + c*8);
        }
#pragma unroll
        for (int i = 0; i < 2; i++) {             // Vt: 64 hd-rows x 8 chunks
            const int id = tid + 256*i;
            const int r = id >> 3, c = id & 7;
            cpa16(&Vsb[r*KLH + c*8], Vg + (size_t)r*SS + c*8);
        }
        CP_COMMIT;
    }

    uint32_t qa[4][4];              // hoisted Q fragments (half2, pre-scaled)
    float s[8][4], o[8][4], mrow[2], lrow_l[2];
#pragma unroll
    for (int hi = 0; hi < 2; hi++) { mrow[hi] = -1e30f; lrow_l[hi] = 0.f; }
#pragma unroll
    for (int ni = 0; ni < 8; ni++)
#pragma unroll
        for (int c = 0; c < 4; c++) o[ni][c] = 0.f;

    const int rb = 16*warp;

    const int nkt = 2*qt + 2;
    for (int kt = 0; kt < nkt; kt++) {
        CP_WAIT0;
        __syncthreads();
        const int st = kt & 1;
        if (kt + 1 < nkt) {                      // prefetch next K/V tile
            const int k1 = (kt + 1) * 64;
            __half* Kd = Ksb + (st^1)*64*KLH;
            __half* Vd = Vsb + (st^1)*64*KLH;
#pragma unroll
            for (int i = 0; i < 2; i++) {
                const int id = tid + 256*i;
                const int r = id >> 3, c = id & 7;
                cpa16(&Kd[r*KLH + c*8], Kg + (size_t)(k1 + r)*DD + c*8);
            }
#pragma unroll
            for (int i = 0; i < 2; i++) {
                const int id = tid + 256*i;
                const int r = id >> 3, c = id & 7;
                cpa16(&Vd[r*KLH + c*8], Vg + (size_t)r*SS + k1 + c*8);
            }
            CP_COMMIT;
        }
        if (kt == 0) {                           // hoist Q frags via ldmatrix
#pragma unroll
            for (int kk = 0; kk < 4; kk++)
                ldsm4(qa[kk][0], qa[kk][1], qa[kk][2], qa[kk][3],
                      &Qs[(rb + lrow)*KLH + 16*kk + khalf]);
        }
        const __half* Ks = Ksb + st*64*KLH;
        const __half* Vs = Vsb + st*64*KLH;
        const int k0 = kt * 64;

        // ---- S = (Q/8) @ K^T; K frags via ldmatrix ----
#pragma unroll
        for (int ni = 0; ni < 8; ni++)
#pragma unroll
            for (int c = 0; c < 4; c++) s[ni][c] = 0.f;

#pragma unroll
        for (int kk = 0; kk < 4; kk++) {
            uint32_t b0[8], b1[8];
#pragma unroll
            for (int nip = 0; nip < 4; nip++)
                ldsm4(b0[2*nip], b0[2*nip+1], b1[2*nip], b1[2*nip+1],
                      &Ks[(16*nip + lrow)*KLH + 16*kk + khalf]);
#pragma unroll
            for (int ni = 0; ni < 8; ni++)
                mma_f16(s[ni][0], s[ni][1], s[ni][2], s[ni][3],
                        qa[kk][0], qa[kk][1], qa[kk][2], qa[kk][3],
                        b0[ni], b1[ni]);
        }

        // ---- online softmax (scores pre-scaled; 4-lane groups = row) ----
        const bool need_mask = (k0 + 63 > q0);
#pragma unroll
        for (int hi = 0; hi < 2; hi++) {
            const int row = q0 + rb + g + 8*hi;
            float mx = -1e30f;
#pragma unroll
            for (int ni = 0; ni < 8; ni++) {
#pragma unroll
                for (int cc = 0; cc < 2; cc++) {
                    float v = s[ni][2*hi+cc];
                    if (need_mask && (k0 + 8*ni + 2*tig + cc > row)) v = -1e30f;
                    s[ni][2*hi+cc] = v;
                    mx = fmaxf(mx, v);
                }
            }
            mx = fmaxf(mx, __shfl_xor_sync(0xffffffffu, mx, 1));
            mx = fmaxf(mx, __shfl_xor_sync(0xffffffffu, mx, 2));
            const float mn = fmaxf(mrow[hi], mx);
            const float alpha = __expf(mrow[hi] - mn);
            mrow[hi] = mn;
            float rs = 0.f;
#pragma unroll
            for (int ni = 0; ni < 8; ni++) {
#pragma unroll
                for (int cc = 0; cc < 2; cc++) {
                    const float p = __expf(s[ni][2*hi+cc] - mn);
                    s[ni][2*hi+cc] = p;
                    rs += p;
                }
            }
            rs += __shfl_xor_sync(0xffffffffu, rs, 1);
            rs += __shfl_xor_sync(0xffffffffu, rs, 2);
            lrow_l[hi] = lrow_l[hi]*alpha + rs;
#pragma unroll
            for (int ni = 0; ni < 8; ni++) {
                o[ni][2*hi+0] *= alpha;
                o[ni][2*hi+1] *= alpha;
            }
        }

        // ---- O += P @ V; Vt frags via ldmatrix, A packed from S regs ----
#pragma unroll
        for (int kk = 0; kk < 4; kk++) {
            uint32_t b0[8], b1[8];
#pragma unroll
            for (int nip = 0; nip < 4; nip++)
                ldsm4(b0[2*nip], b0[2*nip+1], b1[2*nip], b1[2*nip+1],
                      &Vs[(16*nip + lrow)*KLH + 16*kk + khalf]);
            const uint32_t pa0 = packh2(s[2*kk][0],   s[2*kk][1]);
            const uint32_t pa1 = packh2(s[2*kk][2],   s[2*kk][3]);
            const uint32_t pa2 = packh2(s[2*kk+1][0], s[2*kk+1][1]);
            const uint32_t pa3 = packh2(s[2*kk+1][2], s[2*kk+1][3]);
#pragma unroll
            for (int ni = 0; ni < 8; ni++)
                mma_f16(o[ni][0], o[ni][1], o[ni][2], o[ni][3],
                        pa0, pa1, pa2, pa3, b0[ni], b1[ni]);
        }
    }

    // ---- normalize + write ctx [b, s, h*64+hd] fp16 ----
#pragma unroll
    for (int hi = 0; hi < 2; hi++) {
        const float inv = 1.f / lrow_l[hi];
        const int row = q0 + rb + g + 8*hi;
        __half* dst = g_ctxh + ((size_t)b * SS + row) * DD + h * HDD;
#pragma unroll
        for (int ni = 0; ni < 8; ni++) {
            *(__half2*)(dst + 8*ni + 2*tig) =
                __floats2half2_rn(o[ni][2*hi+0]*inv, o[ni][2*hi+1]*inv);
        }
    }
}

// ---------------------------------------------------------------------------
extern "C" void kernel_launch(void* const* d_in, const int* in_sizes, int n_in,
                              void* d_out, int out_size)
{
    const float* x  = (const float*)d_in[0];
    const float* wq = (const float*)d_in[1];
    const float* wk = (const float*)d_in[2];
    const float* wv = (const float*)d_in[3];
    const float* wo = (const float*)d_in[4];
    const float* bo = (const float*)d_in[5];
    float* out = (float*)d_out;

    __half *gqkvh, *gctxh, *gxh, *gwh;
    cudaGetSymbolAddress((void**)&gqkvh, g_qkvh);
    cudaGetSymbolAddress((void**)&gctxh, g_ctxh);
    cudaGetSymbolAddress((void**)&gxh,   g_xh);
    cudaGetSymbolAddress((void**)&gwh,   g_wh);

    const int gemm_smem = 4 * GSTGH * (int)sizeof(__half);      // 73728
    cudaFuncSetAttribute(gemm_f16,
                         cudaFuncAttributeMaxDynamicSharedMemorySize, gemm_smem);
    const int attn_smem = (128*KLH + 4*64*KLH) * (int)sizeof(__half); // 55296
    cudaFuncSetAttribute(attn_f16,
                         cudaFuncAttributeMaxDynamicSharedMemorySize, attn_smem);

    // convert x + all 4 weights to fp16, one fused launch
    const int nx4 = BB*SS*DD/4;
    conv_half<<<dim3((nx4+255)/256, 5), 256>>>(
        (const float4*)x, (const float4*)wq, (const float4*)wk,
        (const float4*)wv, (const float4*)wo, gxh, gwh);

    dim3 gblock(256);

    // fused QKV projection: z selects weight + output slice/layout
    gemm_f16<<<dim3(DD/128, (BB*SS)/128, 3), gblock, gemm_smem>>>(
        gxh, gwh, nullptr, nullptr, gqkvh, 1);

    attn_f16<<<dim3(SS/128, BB*HH), 256, attn_smem>>>();

    gemm_f16<<<dim3(DD/128, (BB*SS)/128, 1), gblock, gemm_smem>>>(
        gctxh, gwh + 3*(size_t)DD*DD, bo, out, nullptr, 0);
}

// round 11
// speedup vs baseline: 1.0227x; 1.0227x over previous
#include <cuda_runtime.h>
#include <cuda_fp16.h>
#include <cstdint>

#define BB 2
#define SS 4096
#define DD 768
#define HH 12
#define HDD 64

// Scratch (device globals: no allocations allowed in kernel_launch)
__device__ __half g_qkvh[3*BB*SS*DD];  // q(x0.125*log2e) | k | vT[b][h][hd][s]
__device__ __half g_ctxh[BB*SS*DD];    // attn output, fp16
__device__ __half g_xh[BB*SS*DD];      // fp16 x
__device__ __half g_wh[4*DD*DD];       // fp16 wq,wk,wv,wo

#define QSCALE 0.1803368802f          // 0.125 * log2(e): softmax in exp2 domain

__device__ __forceinline__ uint32_t packh2(float lo, float hi) {
    __half2 h = __floats2half2_rn(lo, hi);
    return *reinterpret_cast<uint32_t*>(&h);
}

__device__ __forceinline__ void mma_f16(
    float& d0, float& d1, float& d2, float& d3,
    uint32_t a0, uint32_t a1, uint32_t a2, uint32_t a3,
    uint32_t b0, uint32_t b1)
{
    asm volatile(
        "mma.sync.aligned.m16n8k16.row.col.f32.f16.f16.f32 "
        "{%0,%1,%2,%3}, {%4,%5,%6,%7}, {%8,%9}, {%0,%1,%2,%3};\n"
        : "+f"(d0), "+f"(d1), "+f"(d2), "+f"(d3)
        : "r"(a0), "r"(a1), "r"(a2), "r"(a3), "r"(b0), "r"(b1));
}

// ldmatrix x4 from a PRE-COMPUTED shared-memory byte address (no cvta inside)
__device__ __forceinline__ void ldsm4a(
    uint32_t& r0, uint32_t& r1, uint32_t& r2, uint32_t& r3, uint32_t addr)
{
    asm volatile("ldmatrix.sync.aligned.m8n8.x4.shared.b16 {%0,%1,%2,%3}, [%4];"
                 : "=r"(r0), "=r"(r1), "=r"(r2), "=r"(r3) : "r"(addr));
}

__device__ __forceinline__ void cpa16(void* dst, const void* src) {
    uint32_t d = (uint32_t)__cvta_generic_to_shared(dst);
    asm volatile("cp.async.ca.shared.global [%0], [%1], 16;\n" :: "r"(d), "l"(src));
}
#define CP_COMMIT asm volatile("cp.async.commit_group;\n" ::: "memory")
#define CP_WAIT0  asm volatile("cp.async.wait_group 0;\n" ::: "memory")

// ---------------------------------------------------------------------------
// fused fp32 -> fp16 conversion: blockIdx.y selects x / wq / wk / wv / wo
// ---------------------------------------------------------------------------
__global__ void conv_half(const float4* __restrict__ x,
                          const float4* __restrict__ wq, const float4* __restrict__ wk,
                          const float4* __restrict__ wv, const float4* __restrict__ wo,
                          __half* __restrict__ xh, __half* __restrict__ wh)
{
    const int nx4 = BB*SS*DD/4, nw4 = DD*DD/4;
    const int z = blockIdx.y;
    const float4* src; __half* dst; int n4;
    if (z == 0) { src = x; dst = xh; n4 = nx4; }
    else {
        src = (z == 1) ? wq : (z == 2) ? wk : (z == 3) ? wv : wo;
        dst = wh + (size_t)(z-1) * DD*DD;
        n4 = nw4;
    }
    int i = blockIdx.x * blockDim.x + threadIdx.x;
    if (i < n4) {
        float4 v = src[i];
        __half2* d2 = (__half2*)(dst + 4*(size_t)i);
        d2[0] = __floats2half2_rn(v.x, v.y);
        d2[1] = __floats2half2_rn(v.z, v.w);
    }
}

// ---------------------------------------------------------------------------
// fp16 GEMM: C[M,N] = A[M,K] @ W[N,K]^T (+bias). CTA 128x128, BK=64,
// 8 warps (2x4) of 64x32, m16n8k16 mma, fragments via ldmatrix.x4 with
// hoisted per-lane addresses. 2-stage cp.async pipeline (R5/R8 structure).
// Stride 72 halves (144B, ==16 mod 128): 8x8 tile rows hit banks 4r..4r+3.
// mode==0: fp32 out + bias.  mode==1: QKV via blockIdx.z:
//   Q (xQSCALE) | K plain | V transposed vt[b][h][hd][s].
// ---------------------------------------------------------------------------
#define GLH 72
#define GSTGH (128*GLH)

__global__ __launch_bounds__(256) void gemm_f16(
    const __half* __restrict__ A, const __half* __restrict__ Wbase,
    const float* __restrict__ bias, float* __restrict__ Cf,
    __half* __restrict__ Ch, int mode)
{
    extern __shared__ __half hsm[];
    __half* As = hsm;                 // 2 stages x 128 x GLH
    __half* Ws = hsm + 2*GSTGH;

    const int K = DD, N = DD;
    const __half* W = Wbase + (size_t)blockIdx.z * DD*DD;

    const int tid  = threadIdx.x;
    const int lane = tid & 31;
    const int warp = tid >> 5;
    const int g = lane >> 2, tig = lane & 3;
    const int wm = warp & 1;
    const int wn = warp >> 1;
    const int bm = blockIdx.y * 128;
    const int bn = blockIdx.x * 128;

    // hoisted ldmatrix per-lane byte offset: row (lane&15), +8 halves for hi mats
    const uint32_t smb = (uint32_t)__cvta_generic_to_shared(hsm);
    const uint32_t laneoff = (uint32_t)((lane & 15)*144 + ((lane >> 4) << 4));
    const uint32_t aBase0 = smb + (uint32_t)(64*wm)*144 + laneoff;
    const uint32_t wBase0 = smb + (uint32_t)(4*GSTGH) + (uint32_t)(32*wn)*144 + laneoff;

    float acc[4][4][4];
#pragma unroll
    for (int mi = 0; mi < 4; mi++)
#pragma unroll
        for (int ni = 0; ni < 4; ni++)
#pragma unroll
            for (int c = 0; c < 4; c++) acc[mi][ni][c] = 0.f;

    const int nk = K / 64;            // 12

    {
#pragma unroll
        for (int i = 0; i < 8; i++) {
            const int id = tid + 256*i;
            if (id < 1024) {          // A: 128 rows x 8 chunks of 8 halves
                const int r = id >> 3, c = id & 7;
                cpa16(&As[r*GLH + c*8], A + (size_t)(bm + r)*K + c*8);
            } else {
                const int id2 = id - 1024, r = id2 >> 3, c = id2 & 7;
                cpa16(&Ws[r*GLH + c*8], W + (size_t)(bn + r)*K + c*8);
            }
        }
        CP_COMMIT;
    }

    for (int it = 0; it < nk; it++) {
        CP_WAIT0;
        __syncthreads();
        const int s = it & 1;
        if (it + 1 < nk) {
            const int k1 = (it + 1) * 64;
            __half* Ad = As + (s^1)*GSTGH;
            __half* Wd = Ws + (s^1)*GSTGH;
#pragma unroll
            for (int i = 0; i < 8; i++) {
                const int id = tid + 256*i;
                if (id < 1024) {
                    const int r = id >> 3, c = id & 7;
                    cpa16(&Ad[r*GLH + c*8], A + (size_t)(bm + r)*K + k1 + c*8);
                } else {
                    const int id2 = id - 1024, r = id2 >> 3, c = id2 & 7;
                    cpa16(&Wd[r*GLH + c*8], W + (size_t)(bn + r)*K + k1 + c*8);
                }
            }
            CP_COMMIT;
        }
        const uint32_t aB = aBase0 + (uint32_t)s * (2*GSTGH);
        const uint32_t wB = wBase0 + (uint32_t)s * (2*GSTGH);
#pragma unroll
        for (int kk = 0; kk < 4; kk++) {     // 4 k-chunks of 16
            uint32_t b0[4], b1[4];
#pragma unroll
            for (int nip = 0; nip < 2; nip++)
                ldsm4a(b0[2*nip], b0[2*nip+1], b1[2*nip], b1[2*nip+1],
                       wB + nip*(16*144) + kk*32);
#pragma unroll
            for (int mi = 0; mi < 4; mi++) {
                uint32_t a0, a1, a2, a3;
                ldsm4a(a0, a1, a2, a3, aB + mi*(16*144) + kk*32);
#pragma unroll
                for (int ni = 0; ni < 4; ni++)
                    mma_f16(acc[mi][ni][0], acc[mi][ni][1],
                            acc[mi][ni][2], acc[mi][ni][3],
                            a0, a1, a2, a3, b0[ni], b1[ni]);
            }
        }
    }

    const int z = blockIdx.z;
#pragma unroll
    for (int ni = 0; ni < 4; ni++) {
        const int col = bn + 32*wn + 8*ni + 2*tig;
        float bx = 0.f, by = 0.f;
        if (mode == 0 && bias) { bx = bias[col]; by = bias[col+1]; }
#pragma unroll
        for (int mi = 0; mi < 4; mi++) {
            const int r0 = bm + 64*wm + 16*mi + g;
            float v0 = acc[mi][ni][0] + bx, v1 = acc[mi][ni][1] + by;
            float v2 = acc[mi][ni][2] + bx, v3 = acc[mi][ni][3] + by;
            if (mode == 0) {
                *(float2*)(Cf + (size_t)r0*N + col)     = make_float2(v0, v1);
                *(float2*)(Cf + (size_t)(r0+8)*N + col) = make_float2(v2, v3);
                continue;
            }
            __half* C = Ch + (size_t)z * BB*SS*DD;
            if (z == 0) {                 // Q, pre-scaled for exp2-domain softmax
                v0 *= QSCALE; v1 *= QSCALE; v2 *= QSCALE; v3 *= QSCALE;
            }
            if (z <= 1) {                 // Q/K: plain [s][768] fp16
                *(__half2*)(C + (size_t)r0*N + col) = __floats2half2_rn(v0, v1);
                *(__half2*)(C + (size_t)(r0+8)*N + col) = __floats2half2_rn(v2, v3);
            } else {                      // V transposed: vt[((b*HH+h)*64+hd)][s]
                const int h = col >> 6, hd = col & 63;
#pragma unroll
                for (int rr = 0; rr < 2; rr++) {
                    const int r = r0 + 8*rr;
                    const int b = r >> 12, sq = r & (SS-1);
                    __half* vp = C + ((size_t)((b*HH + h)*HDD + hd))*SS + sq;
                    vp[0]  = __float2half_rn(rr ? v2 : v0);
                    vp[SS] = __float2half_rn(rr ? v3 : v1);
                }
            }
        }
    }
}

// ---------------------------------------------------------------------------
// Flash attention, fp16 m16n8k16 mma, fp32 accum, exp2-domain softmax.
// 8 warps (16-row bands), BQ=128, BK=64; K/V double-buffered cp.async.
// K and V^T fragments via ldmatrix.x4 with hoisted addresses.
// Conditional alpha-rescale: skipped when no row in the warp updates its max.
// ---------------------------------------------------------------------------
#define KLH 72

__global__ __launch_bounds__(256, 2) void attn_f16()
{
    extern __shared__ __half hsmm[];
    __half* Qs  = hsmm;                       // 128 x KLH
    __half* Ksb = hsmm + 128*KLH;             // 2 x 64 x KLH
    __half* Vsb = Ksb + 2*64*KLH;             // 2 x 64(hd) x KLH (keys)

    const int tid  = threadIdx.x;
    const int lane = tid & 31;
    const int warp = tid >> 5;                // 0..7 -> 16-row band
    const int g = lane >> 2, tig = lane & 3;
    const int bh = blockIdx.y;
    const int b  = bh / HH;
    const int h  = bh % HH;
    const int qt = (gridDim.x - 1) - blockIdx.x;   // heavy tiles first
    const int q0 = qt * 128;

    const __half* Qg = g_qkvh + 0*BB*SS*DD + ((size_t)b * SS) * DD + h * HDD;
    const __half* Kg = g_qkvh + 1*BB*SS*DD + ((size_t)b * SS) * DD + h * HDD;
    const __half* Vg = g_qkvh + 2*BB*SS*DD + ((size_t)(b*HH + h) * HDD) * SS;

    // hoisted ldmatrix per-lane byte addresses
    const uint32_t smb = (uint32_t)__cvta_generic_to_shared(hsmm);
    const uint32_t laneoff = (uint32_t)((lane & 15)*144 + ((lane >> 4) << 4));
    const uint32_t qAddr  = smb + (uint32_t)(16*warp)*144 + laneoff;
    const uint32_t kBase0 = smb + (uint32_t)(128*144) + laneoff;
    const uint32_t vBase0 = kBase0 + (uint32_t)(2*64*144);

    // prologue: Q tile + K/V tile 0
    {
#pragma unroll
        for (int i = 0; i < 4; i++) {             // Q: 128 rows x 8 chunks
            const int id = tid + 256*i;
            const int r = id >> 3, c = id & 7;
            cpa16(&Qs[r*KLH + c*8], Qg + (size_t)(q0 + r)*DD + c*8);
        }
#pragma unroll
        for (int i = 0; i < 2; i++) {             // K: 64 rows x 8 chunks
            const int id = tid + 256*i;
            const int r = id >> 3, c = id & 7;
            cpa16(&Ksb[r*KLH + c*8], Kg + (size_t)r*DD + c*8);
        }
#pragma unroll
        for (int i = 0; i < 2; i++) {             // Vt: 64 hd-rows x 8 chunks
            const int id = tid + 256*i;
            const int r = id >> 3, c = id & 7;
            cpa16(&Vsb[r*KLH + c*8], Vg + (size_t)r*SS + c*8);
        }
        CP_COMMIT;
    }

    uint32_t qa[4][4];              // hoisted Q fragments (half2, pre-scaled)
    float s[8][4], o[8][4], mrow[2], lrow[2];
#pragma unroll
    for (int hi = 0; hi < 2; hi++) { mrow[hi] = -1e30f; lrow[hi] = 0.f; }
#pragma unroll
    for (int ni = 0; ni < 8; ni++)
#pragma unroll
        for (int c = 0; c < 4; c++) o[ni][c] = 0.f;

    const int rb = 16*warp;

    const int nkt = 2*qt + 2;
    for (int kt = 0; kt < nkt; kt++) {
        CP_WAIT0;
        __syncthreads();
        const int st = kt & 1;
        if (kt + 1 < nkt) {                      // prefetch next K/V tile
            const int k1 = (kt + 1) * 64;
            __half* Kd = Ksb + (st^1)*64*KLH;
            __half* Vd = Vsb + (st^1)*64*KLH;
#pragma unroll
            for (int i = 0; i < 2; i++) {
                const int id = tid + 256*i;
                const int r = id >> 3, c = id & 7;
                cpa16(&Kd[r*KLH + c*8], Kg + (size_t)(k1 + r)*DD + c*8);
            }
#pragma unroll
            for (int i = 0; i < 2; i++) {
                const int id = tid + 256*i;
                const int r = id >> 3, c = id & 7;
                cpa16(&Vd[r*KLH + c*8], Vg + (size_t)r*SS + k1 + c*8);
            }
            CP_COMMIT;
        }
        if (kt == 0) {                           // hoist Q frags via ldmatrix
#pragma unroll
            for (int kk = 0; kk < 4; kk++)
                ldsm4a(qa[kk][0], qa[kk][1], qa[kk][2], qa[kk][3],
                       qAddr + kk*32);
        }
        const uint32_t kB = kBase0 + (uint32_t)st*(64*144);
        const uint32_t vB = vBase0 + (uint32_t)st*(64*144);
        const int k0 = kt * 64;

        // ---- S = Qs @ K^T (scores already in exp2 domain) ----
#pragma unroll
        for (int ni = 0; ni < 8; ni++)
#pragma unroll
            for (int c = 0; c < 4; c++) s[ni][c] = 0.f;

#pragma unroll
        for (int kk = 0; kk < 4; kk++) {
            uint32_t b0[8], b1[8];
#pragma unroll
            for (int nip = 0; nip < 4; nip++)
                ldsm4a(b0[2*nip], b0[2*nip+1], b1[2*nip], b1[2*nip+1],
                       kB + nip*(16*144) + kk*32);
#pragma unroll
            for (int ni = 0; ni < 8; ni++)
                mma_f16(s[ni][0], s[ni][1], s[ni][2], s[ni][3],
                        qa[kk][0], qa[kk][1], qa[kk][2], qa[kk][3],
                        b0[ni], b1[ni]);
        }

        // ---- online softmax, exp2 domain ----
        const bool need_mask = (k0 + 63 > q0);
        float mn[2];
#pragma unroll
        for (int hi = 0; hi < 2; hi++) {
            const int row = q0 + rb + g + 8*hi;
            float mx = -1e30f;
#pragma unroll
            for (int ni = 0; ni < 8; ni++) {
#pragma unroll
                for (int cc = 0; cc < 2; cc++) {
                    float v = s[ni][2*hi+cc];
                    if (need_mask && (k0 + 8*ni + 2*tig + cc > row)) v = -1e30f;
                    s[ni][2*hi+cc] = v;
                    mx = fmaxf(mx, v);
                }
            }
            mx = fmaxf(mx, __shfl_xor_sync(0xffffffffu, mx, 1));
            mx = fmaxf(mx, __shfl_xor_sync(0xffffffffu, mx, 2));
            mn[hi] = fmaxf(mrow[hi], mx);
        }
        // rescale only if some row in the warp raised its max (exact skip)
        const bool upd = (mn[0] > mrow[0]) | (mn[1] > mrow[1]);
        if (__ballot_sync(0xffffffffu, upd)) {
#pragma unroll
            for (int hi = 0; hi < 2; hi++) {
                const float alpha = exp2f(mrow[hi] - mn[hi]);
                mrow[hi] = mn[hi];
                lrow[hi] *= alpha;
#pragma unroll
                for (int ni = 0; ni < 8; ni++) {
                    o[ni][2*hi+0] *= alpha;
                    o[ni][2*hi+1] *= alpha;
                }
            }
        }
#pragma unroll
        for (int hi = 0; hi < 2; hi++) {
            float rs = 0.f;
#pragma unroll
            for (int ni = 0; ni < 8; ni++) {
#pragma unroll
                for (int cc = 0; cc < 2; cc++) {
                    const float p = exp2f(s[ni][2*hi+cc] - mrow[hi]);
                    s[ni][2*hi+cc] = p;
                    rs += p;
                }
            }
            rs += __shfl_xor_sync(0xffffffffu, rs, 1);
            rs += __shfl_xor_sync(0xffffffffu, rs, 2);
            lrow[hi] += rs;
        }

        // ---- O += P @ V; Vt frags via ldmatrix, A packed from S regs ----
#pragma unroll
        for (int kk = 0; kk < 4; kk++) {
            uint32_t b0[8], b1[8];
#pragma unroll
            for (int nip = 0; nip < 4; nip++)
                ldsm4a(b0[2*nip], b0[2*nip+1], b1[2*nip], b1[2*nip+1],
                       vB + nip*(16*144) + kk*32);
            const uint32_t pa0 = packh2(s[2*kk][0],   s[2*kk][1]);
            const uint32_t pa1 = packh2(s[2*kk][2],   s[2*kk][3]);
            const uint32_t pa2 = packh2(s[2*kk+1][0], s[2*kk+1][1]);
            const uint32_t pa3 = packh2(s[2*kk+1][2], s[2*kk+1][3]);
#pragma unroll
            for (int ni = 0; ni < 8; ni++)
                mma_f16(o[ni][0], o[ni][1], o[ni][2], o[ni][3],
                        pa0, pa1, pa2, pa3, b0[ni], b1[ni]);
        }
    }

    // ---- normalize + write ctx [b, s, h*64+hd] fp16 ----
#pragma unroll
    for (int hi = 0; hi < 2; hi++) {
        const float inv = 1.f / lrow[hi];
        const int row = q0 + rb + g + 8*hi;
        __half* dst = g_ctxh + ((size_t)b * SS + row) * DD + h * HDD;
#pragma unroll
        for (int ni = 0; ni < 8; ni++) {
            *(__half2*)(dst + 8*ni + 2*tig) =
                __floats2half2_rn(o[ni][2*hi+0]*inv, o[ni][2*hi+1]*inv);
        }
    }
}

// ---------------------------------------------------------------------------
extern "C" void kernel_launch(void* const* d_in, const int* in_sizes, int n_in,
                              void* d_out, int out_size)
{
    const float* x  = (const float*)d_in[0];
    const float* wq = (const float*)d_in[1];
    const float* wk = (const float*)d_in[2];
    const float* wv = (const float*)d_in[3];
    const float* wo = (const float*)d_in[4];
    const float* bo = (const float*)d_in[5];
    float* out = (float*)d_out;

    __half *gqkvh, *gctxh, *gxh, *gwh;
    cudaGetSymbolAddress((void**)&gqkvh, g_qkvh);
    cudaGetSymbolAddress((void**)&gctxh, g_ctxh);
    cudaGetSymbolAddress((void**)&gxh,   g_xh);
    cudaGetSymbolAddress((void**)&gwh,   g_wh);

    const int gemm_smem = 4 * GSTGH * (int)sizeof(__half);      // 73728
    cudaFuncSetAttribute(gemm_f16,
                         cudaFuncAttributeMaxDynamicSharedMemorySize, gemm_smem);
    const int attn_smem = (128*KLH + 4*64*KLH) * (int)sizeof(__half); // 55296
    cudaFuncSetAttribute(attn_f16,
                         cudaFuncAttributeMaxDynamicSharedMemorySize, attn_smem);

    // convert x + all 4 weights to fp16, one fused launch
    const int nx4 = BB*SS*DD/4;
    conv_half<<<dim3((nx4+255)/256, 5), 256>>>(
        (const float4*)x, (const float4*)wq, (const float4*)wk,
        (const float4*)wv, (const float4*)wo, gxh, gwh);

    dim3 gblock(256);

    // fused QKV projection: z selects weight + output slice/layout
    gemm_f16<<<dim3(DD/128, (BB*SS)/128, 3), gblock, gemm_smem>>>(
        gxh, gwh, nullptr, nullptr, gqkvh, 1);

    attn_f16<<<dim3(SS/128, BB*HH), 256, attn_smem>>>();

    gemm_f16<<<dim3(DD/128, (BB*SS)/128, 1), gblock, gemm_smem>>>(
        gctxh, gwh + 3*(size_t)DD*DD, bo, out, nullptr, 0);
}

// round 12
// speedup vs baseline: 1.0345x; 1.0115x over previous
#include <cuda_runtime.h>
#include <cuda_fp16.h>
#include <cstdint>

#define BB 2
#define SS 4096
#define DD 768
#define HH 12
#define HDD 64

// Scratch (device globals: no allocations allowed in kernel_launch)
__device__ __half g_qkvh[3*BB*SS*DD];  // q(x0.125*log2e) | k | vT[b][h][hd][s]
__device__ __half g_ctxh[BB*SS*DD];    // attn output, fp16
__device__ __half g_xh[BB*SS*DD];      // fp16 x
__device__ __half g_wh[4*DD*DD];       // fp16 wq,wk,wv,wo

#define QSCALE 0.1803368802f          // 0.125 * log2(e): softmax in exp2 domain

__device__ __forceinline__ uint32_t packh2(float lo, float hi) {
    __half2 h = __floats2half2_rn(lo, hi);
    return *reinterpret_cast<uint32_t*>(&h);
}

__device__ __forceinline__ void mma_f16(
    float& d0, float& d1, float& d2, float& d3,
    uint32_t a0, uint32_t a1, uint32_t a2, uint32_t a3,
    uint32_t b0, uint32_t b1)
{
    asm volatile(
        "mma.sync.aligned.m16n8k16.row.col.f32.f16.f16.f32 "
        "{%0,%1,%2,%3}, {%4,%5,%6,%7}, {%8,%9}, {%0,%1,%2,%3};\n"
        : "+f"(d0), "+f"(d1), "+f"(d2), "+f"(d3)
        : "r"(a0), "r"(a1), "r"(a2), "r"(a3), "r"(b0), "r"(b1));
}

// ldmatrix x4 from a PRE-COMPUTED shared-memory byte address (attn only)
__device__ __forceinline__ void ldsm4a(
    uint32_t& r0, uint32_t& r1, uint32_t& r2, uint32_t& r3, uint32_t addr)
{
    asm volatile("ldmatrix.sync.aligned.m8n8.x4.shared.b16 {%0,%1,%2,%3}, [%4];"
                 : "=r"(r0), "=r"(r1), "=r"(r2), "=r"(r3) : "r"(addr));
}

__device__ __forceinline__ void cpa16(void* dst, const void* src) {
    uint32_t d = (uint32_t)__cvta_generic_to_shared(dst);
    asm volatile("cp.async.ca.shared.global [%0], [%1], 16;\n" :: "r"(d), "l"(src));
}
#define CP_COMMIT asm volatile("cp.async.commit_group;\n" ::: "memory")
#define CP_WAIT0  asm volatile("cp.async.wait_group 0;\n" ::: "memory")

// ---------------------------------------------------------------------------
// fused fp32 -> fp16 conversion: blockIdx.y selects x / wq / wk / wv / wo
// ---------------------------------------------------------------------------
__global__ void conv_half(const float4* __restrict__ x,
                          const float4* __restrict__ wq, const float4* __restrict__ wk,
                          const float4* __restrict__ wv, const float4* __restrict__ wo,
                          __half* __restrict__ xh, __half* __restrict__ wh)
{
    const int nx4 = BB*SS*DD/4, nw4 = DD*DD/4;
    const int z = blockIdx.y;
    const float4* src; __half* dst; int n4;
    if (z == 0) { src = x; dst = xh; n4 = nx4; }
    else {
        src = (z == 1) ? wq : (z == 2) ? wk : (z == 3) ? wv : wo;
        dst = wh + (size_t)(z-1) * DD*DD;
        n4 = nw4;
    }
    int i = blockIdx.x * blockDim.x + threadIdx.x;
    if (i < n4) {
        float4 v = src[i];
        __half2* d2 = (__half2*)(dst + 4*(size_t)i);
        d2[0] = __floats2half2_rn(v.x, v.y);
        d2[1] = __floats2half2_rn(v.z, v.w);
    }
}

// ---------------------------------------------------------------------------
// fp16 GEMM: C[M,N] = A[M,K] @ W[N,K]^T (+bias). CTA 128x128, BK=64,
// 8 warps (2x4) of 64x32, m16n8k16 fp16 mma with fp32 accumulation.
// Fragment loads: R9-proven scalar LDS.32 pattern (stride 36 words ==4 mod 32
// -> banks 4g+tig, conflict-free; measured 40.4us @ alu 6.2%).
// 2-stage cp.async pipeline (R5/R8-proven loop structure).
// mode==0: fp32 out + bias (out-proj).  mode==1: QKV via blockIdx.z:
//   Q (xQSCALE) | K plain | V transposed vt[b][h][hd][s].
// ---------------------------------------------------------------------------
#define GLH 72
#define GSTGH (128*GLH)

__global__ __launch_bounds__(256) void gemm_f16(
    const __half* __restrict__ A, const __half* __restrict__ Wbase,
    const float* __restrict__ bias, float* __restrict__ Cf,
    __half* __restrict__ Ch, int mode)
{
    extern __shared__ __half hsm[];
    __half* As = hsm;                 // 2 stages x 128 x GLH
    __half* Ws = hsm + 2*GSTGH;

    const int K = DD, N = DD;
    const __half* W = Wbase + (size_t)blockIdx.z * DD*DD;

    const int tid  = threadIdx.x;
    const int lane = tid & 31;
    const int warp = tid >> 5;
    const int g = lane >> 2, tig = lane & 3;
    const int wm = warp & 1;
    const int wn = warp >> 1;
    const int bm = blockIdx.y * 128;
    const int bn = blockIdx.x * 128;

    float acc[4][4][4];
#pragma unroll
    for (int mi = 0; mi < 4; mi++)
#pragma unroll
        for (int ni = 0; ni < 4; ni++)
#pragma unroll
            for (int c = 0; c < 4; c++) acc[mi][ni][c] = 0.f;

    const int nk = K / 64;            // 12

    {
#pragma unroll
        for (int i = 0; i < 8; i++) {
            const int id = tid + 256*i;
            if (id < 1024) {          // A: 128 rows x 8 chunks of 8 halves
                const int r = id >> 3, c = id & 7;
                cpa16(&As[r*GLH + c*8], A + (size_t)(bm + r)*K + c*8);
            } else {
                const int id2 = id - 1024, r = id2 >> 3, c = id2 & 7;
                cpa16(&Ws[r*GLH + c*8], W + (size_t)(bn + r)*K + c*8);
            }
        }
        CP_COMMIT;
    }

    for (int it = 0; it < nk; it++) {
        CP_WAIT0;
        __syncthreads();
        const int s = it & 1;
        if (it + 1 < nk) {
            const int k1 = (it + 1) * 64;
            __half* Ad = As + (s^1)*GSTGH;
            __half* Wd = Ws + (s^1)*GSTGH;
#pragma unroll
            for (int i = 0; i < 8; i++) {
                const int id = tid + 256*i;
                if (id < 1024) {
                    const int r = id >> 3, c = id & 7;
                    cpa16(&Ad[r*GLH + c*8], A + (size_t)(bm + r)*K + k1 + c*8);
                } else {
                    const int id2 = id - 1024, r = id2 >> 3, c = id2 & 7;
                    cpa16(&Wd[r*GLH + c*8], W + (size_t)(bn + r)*K + k1 + c*8);
                }
            }
            CP_COMMIT;
        }
        const uint32_t* Ab = (const uint32_t*)(As + s*GSTGH);
        const uint32_t* Wb = (const uint32_t*)(Ws + s*GSTGH);
#pragma unroll
        for (int kk = 0; kk < 4; kk++) {     // 4 k-chunks of 16
            uint32_t b0[4], b1[4];
#pragma unroll
            for (int ni = 0; ni < 4; ni++) {
                const uint32_t* wp = Wb + (32*wn + 8*ni + g)*36 + 8*kk + tig;
                b0[ni] = wp[0];              // W[col][16kk+2tig .. +1]
                b1[ni] = wp[4];              // W[col][16kk+8+2tig .. +1]
            }
#pragma unroll
            for (int mi = 0; mi < 4; mi++) {
                const int rbm = 64*wm + 16*mi;
                const uint32_t* ap0 = Ab + (rbm + g)*36 + 8*kk + tig;
                const uint32_t* ap1 = Ab + (rbm + g + 8)*36 + 8*kk + tig;
                const uint32_t a0 = ap0[0];
                const uint32_t a1 = ap1[0];
                const uint32_t a2 = ap0[4];
                const uint32_t a3 = ap1[4];
#pragma unroll
                for (int ni = 0; ni < 4; ni++)
                    mma_f16(acc[mi][ni][0], acc[mi][ni][1],
                            acc[mi][ni][2], acc[mi][ni][3],
                            a0, a1, a2, a3, b0[ni], b1[ni]);
            }
        }
    }

    const int z = blockIdx.z;
#pragma unroll
    for (int ni = 0; ni < 4; ni++) {
        const int col = bn + 32*wn + 8*ni + 2*tig;
        float bx = 0.f, by = 0.f;
        if (mode == 0 && bias) { bx = bias[col]; by = bias[col+1]; }
#pragma unroll
        for (int mi = 0; mi < 4; mi++) {
            const int r0 = bm + 64*wm + 16*mi + g;
            float v0 = acc[mi][ni][0] + bx, v1 = acc[mi][ni][1] + by;
            float v2 = acc[mi][ni][2] + bx, v3 = acc[mi][ni][3] + by;
            if (mode == 0) {
                *(float2*)(Cf + (size_t)r0*N + col)     = make_float2(v0, v1);
                *(float2*)(Cf + (size_t)(r0+8)*N + col) = make_float2(v2, v3);
                continue;
            }
            __half* C = Ch + (size_t)z * BB*SS*DD;
            if (z == 0) {                 // Q, pre-scaled for exp2-domain softmax
                v0 *= QSCALE; v1 *= QSCALE; v2 *= QSCALE; v3 *= QSCALE;
            }
            if (z <= 1) {                 // Q/K: plain [s][768] fp16
                *(__half2*)(C + (size_t)r0*N + col) = __floats2half2_rn(v0, v1);
                *(__half2*)(C + (size_t)(r0+8)*N + col) = __floats2half2_rn(v2, v3);
            } else {                      // V transposed: vt[((b*HH+h)*64+hd)][s]
                const int h = col >> 6, hd = col & 63;
#pragma unroll
                for (int rr = 0; rr < 2; rr++) {
                    const int r = r0 + 8*rr;
                    const int b = r >> 12, sq = r & (SS-1);
                    __half* vp = C + ((size_t)((b*HH + h)*HDD + hd))*SS + sq;
                    vp[0]  = __float2half_rn(rr ? v2 : v0);
                    vp[SS] = __float2half_rn(rr ? v3 : v1);
                }
            }
        }
    }
}

// ---------------------------------------------------------------------------
// Flash attention, fp16 m16n8k16 mma, fp32 accum, exp2-domain softmax.
// (unchanged from R11 — measured win)
// 8 warps (16-row bands), BQ=128, BK=64; K/V double-buffered cp.async.
// K and V^T fragments via ldmatrix.x4 with hoisted addresses.
// Conditional alpha-rescale: skipped when no row in the warp updates its max.
// ---------------------------------------------------------------------------
#define KLH 72

__global__ __launch_bounds__(256, 2) void attn_f16()
{
    extern __shared__ __half hsmm[];
    __half* Qs  = hsmm;                       // 128 x KLH
    __half* Ksb = hsmm + 128*KLH;             // 2 x 64 x KLH
    __half* Vsb = Ksb + 2*64*KLH;             // 2 x 64(hd) x KLH (keys)

    const int tid  = threadIdx.x;
    const int lane = tid & 31;
    const int warp = tid >> 5;                // 0..7 -> 16-row band
    const int g = lane >> 2, tig = lane & 3;
    const int bh = blockIdx.y;
    const int b  = bh / HH;
    const int h  = bh % HH;
    const int qt = (gridDim.x - 1) - blockIdx.x;   // heavy tiles first
    const int q0 = qt * 128;

    const __half* Qg = g_qkvh + 0*BB*SS*DD + ((size_t)b * SS) * DD + h * HDD;
    const __half* Kg = g_qkvh + 1*BB*SS*DD + ((size_t)b * SS) * DD + h * HDD;
    const __half* Vg = g_qkvh + 2*BB*SS*DD + ((size_t)(b*HH + h) * HDD) * SS;

    // hoisted ldmatrix per-lane byte addresses
    const uint32_t smb = (uint32_t)__cvta_generic_to_shared(hsmm);
    const uint32_t laneoff = (uint32_t)((lane & 15)*144 + ((lane >> 4) << 4));
    const uint32_t qAddr  = smb + (uint32_t)(16*warp)*144 + laneoff;
    const uint32_t kBase0 = smb + (uint32_t)(128*144) + laneoff;
    const uint32_t vBase0 = kBase0 + (uint32_t)(2*64*144);

    // prologue: Q tile + K/V tile 0
    {
#pragma unroll
        for (int i = 0; i < 4; i++) {             // Q: 128 rows x 8 chunks
            const int id = tid + 256*i;
            const int r = id >> 3, c = id & 7;
            cpa16(&Qs[r*KLH + c*8], Qg + (size_t)(q0 + r)*DD + c*8);
        }
#pragma unroll
        for (int i = 0; i < 2; i++) {             // K: 64 rows x 8 chunks
            const int id = tid + 256*i;
            const int r = id >> 3, c = id & 7;
            cpa16(&Ksb[r*KLH + c*8], Kg + (size_t)r*DD + c*8);
        }
#pragma unroll
        for (int i = 0; i < 2; i++) {             // Vt: 64 hd-rows x 8 chunks
            const int id = tid + 256*i;
            const int r = id >> 3, c = id & 7;
            cpa16(&Vsb[r*KLH + c*8], Vg + (size_t)r*SS + c*8);
        }
        CP_COMMIT;
    }

    uint32_t qa[4][4];              // hoisted Q fragments (half2, pre-scaled)
    float s[8][4], o[8][4], mrow[2], lrow[2];
#pragma unroll
    for (int hi = 0; hi < 2; hi++) { mrow[hi] = -1e30f; lrow[hi] = 0.f; }
#pragma unroll
    for (int ni = 0; ni < 8; ni++)
#pragma unroll
        for (int c = 0; c < 4; c++) o[ni][c] = 0.f;

    const int rb = 16*warp;

    const int nkt = 2*qt + 2;
    for (int kt = 0; kt < nkt; kt++) {
        CP_WAIT0;
        __syncthreads();
        const int st = kt & 1;
        if (kt + 1 < nkt) {                      // prefetch next K/V tile
            const int k1 = (kt + 1) * 64;
            __half* Kd = Ksb + (st^1)*64*KLH;
            __half* Vd = Vsb + (st^1)*64*KLH;
#pragma unroll
            for (int i = 0; i < 2; i++) {
                const int id = tid + 256*i;
                const int r = id >> 3, c = id & 7;
                cpa16(&Kd[r*KLH + c*8], Kg + (size_t)(k1 + r)*DD + c*8);
            }
#pragma unroll
            for (int i = 0; i < 2; i++) {
                const int id = tid + 256*i;
                const int r = id >> 3, c = id & 7;
                cpa16(&Vd[r*KLH + c*8], Vg + (size_t)r*SS + k1 + c*8);
            }
            CP_COMMIT;
        }
        if (kt == 0) {                           // hoist Q frags via ldmatrix
#pragma unroll
            for (int kk = 0; kk < 4; kk++)
                ldsm4a(qa[kk][0], qa[kk][1], qa[kk][2], qa[kk][3],
                       qAddr + kk*32);
        }
        const uint32_t kB = kBase0 + (uint32_t)st*(64*144);
        const uint32_t vB = vBase0 + (uint32_t)st*(64*144);
        const int k0 = kt * 64;

        // ---- S = Qs @ K^T (scores already in exp2 domain) ----
#pragma unroll
        for (int ni = 0; ni < 8; ni++)
#pragma unroll
            for (int c = 0; c < 4; c++) s[ni][c] = 0.f;

#pragma unroll
        for (int kk = 0; kk < 4; kk++) {
            uint32_t b0[8], b1[8];
#pragma unroll
            for (int nip = 0; nip < 4; nip++)
                ldsm4a(b0[2*nip], b0[2*nip+1], b1[2*nip], b1[2*nip+1],
                       kB + nip*(16*144) + kk*32);
#pragma unroll
            for (int ni = 0; ni < 8; ni++)
                mma_f16(s[ni][0], s[ni][1], s[ni][2], s[ni][3],
                        qa[kk][0], qa[kk][1], qa[kk][2], qa[kk][3],
                        b0[ni], b1[ni]);
        }

        // ---- online softmax, exp2 domain ----
        const bool need_mask = (k0 + 63 > q0);
        float mn[2];
#pragma unroll
        for (int hi = 0; hi < 2; hi++) {
            const int row = q0 + rb + g + 8*hi;
            float mx = -1e30f;
#pragma unroll
            for (int ni = 0; ni < 8; ni++) {
#pragma unroll
                for (int cc = 0; cc < 2; cc++) {
                    float v = s[ni][2*hi+cc];
                    if (need_mask && (k0 + 8*ni + 2*tig + cc > row)) v = -1e30f;
                    s[ni][2*hi+cc] = v;
                    mx = fmaxf(mx, v);
                }
            }
            mx = fmaxf(mx, __shfl_xor_sync(0xffffffffu, mx, 1));
            mx = fmaxf(mx, __shfl_xor_sync(0xffffffffu, mx, 2));
            mn[hi] = fmaxf(mrow[hi], mx);
        }
        // rescale only if some row in the warp raised its max (exact skip)
        const bool upd = (mn[0] > mrow[0]) | (mn[1] > mrow[1]);
        if (__ballot_sync(0xffffffffu, upd)) {
#pragma unroll
            for (int hi = 0; hi < 2; hi++) {
                const float alpha = exp2f(mrow[hi] - mn[hi]);
                mrow[hi] = mn[hi];
                lrow[hi] *= alpha;
#pragma unroll
                for (int ni = 0; ni < 8; ni++) {
                    o[ni][2*hi+0] *= alpha;
                    o[ni][2*hi+1] *= alpha;
                }
            }
        }
#pragma unroll
        for (int hi = 0; hi < 2; hi++) {
            float rs = 0.f;
#pragma unroll
            for (int ni = 0; ni < 8; ni++) {
#pragma unroll
                for (int cc = 0; cc < 2; cc++) {
                    const float p = exp2f(s[ni][2*hi+cc] - mrow[hi]);
                    s[ni][2*hi+cc] = p;
                    rs += p;
                }
            }
            rs += __shfl_xor_sync(0xffffffffu, rs, 1);
            rs += __shfl_xor_sync(0xffffffffu, rs, 2);
            lrow[hi] += rs;
        }

        // ---- O += P @ V; Vt frags via ldmatrix, A packed from S regs ----
#pragma unroll
        for (int kk = 0; kk < 4; kk++) {
            uint32_t b0[8], b1[8];
#pragma unroll
            for (int nip = 0; nip < 4; nip++)
                ldsm4a(b0[2*nip], b0[2*nip+1], b1[2*nip], b1[2*nip+1],
                       vB + nip*(16*144) + kk*32);
            const uint32_t pa0 = packh2(s[2*kk][0],   s[2*kk][1]);
            const uint32_t pa1 = packh2(s[2*kk][2],   s[2*kk][3]);
            const uint32_t pa2 = packh2(s[2*kk+1][0], s[2*kk+1][1]);
            const uint32_t pa3 = packh2(s[2*kk+1][2], s[2*kk+1][3]);
#pragma unroll
            for (int ni = 0; ni < 8; ni++)
                mma_f16(o[ni][0], o[ni][1], o[ni][2], o[ni][3],
                        pa0, pa1, pa2, pa3, b0[ni], b1[ni]);
        }
    }

    // ---- normalize + write ctx [b, s, h*64+hd] fp16 ----
#pragma unroll
    for (int hi = 0; hi < 2; hi++) {
        const float inv = 1.f / lrow[hi];
        const int row = q0 + rb + g + 8*hi;
        __half* dst = g_ctxh + ((size_t)b * SS + row) * DD + h * HDD;
#pragma unroll
        for (int ni = 0; ni < 8; ni++) {
            *(__half2*)(dst + 8*ni + 2*tig) =
                __floats2half2_rn(o[ni][2*hi+0]*inv, o[ni][2*hi+1]*inv);
        }
    }
}

// ---------------------------------------------------------------------------
extern "C" void kernel_launch(void* const* d_in, const int* in_sizes, int n_in,
                              void* d_out, int out_size)
{
    const float* x  = (const float*)d_in[0];
    const float* wq = (const float*)d_in[1];
    const float* wk = (const float*)d_in[2];
    const float* wv = (const float*)d_in[3];
    const float* wo = (const float*)d_in[4];
    const float* bo = (const float*)d_in[5];
    float* out = (float*)d_out;

    __half *gqkvh, *gctxh, *gxh, *gwh;
    cudaGetSymbolAddress((void**)&gqkvh, g_qkvh);
    cudaGetSymbolAddress((void**)&gctxh, g_ctxh);
    cudaGetSymbolAddress((void**)&gxh,   g_xh);
    cudaGetSymbolAddress((void**)&gwh,   g_wh);

    const int gemm_smem = 4 * GSTGH * (int)sizeof(__half);      // 73728
    cudaFuncSetAttribute(gemm_f16,
                         cudaFuncAttributeMaxDynamicSharedMemorySize, gemm_smem);
    const int attn_smem = (128*KLH + 4*64*KLH) * (int)sizeof(__half); // 55296
    cudaFuncSetAttribute(attn_f16,
                         cudaFuncAttributeMaxDynamicSharedMemorySize, attn_smem);

    // convert x + all 4 weights to fp16, one fused launch
    const int nx4 = BB*SS*DD/4;
    conv_half<<<dim3((nx4+255)/256, 5), 256>>>(
        (const float4*)x, (const float4*)wq, (const float4*)wk,
        (const float4*)wv, (const float4*)wo, gxh, gwh);

    dim3 gblock(256);

    // fused QKV projection: z selects weight + output slice/layout
    gemm_f16<<<dim3(DD/128, (BB*SS)/128, 3), gblock, gemm_smem>>>(
        gxh, gwh, nullptr, nullptr, gqkvh, 1);

    attn_f16<<<dim3(SS/128, BB*HH), 256, attn_smem>>>();

    gemm_f16<<<dim3(DD/128, (BB*SS)/128, 1), gblock, gemm_smem>>>(
        gctxh, gwh + 3*(size_t)DD*DD, bo, out, nullptr, 0);
}